// round 2
// baseline (speedup 1.0000x reference)
#include <cuda_runtime.h>
#include <cstdint>
#include <math.h>

#define SQ 4096
#define DM 768
#define FFD 3072
#define NH 12
#define DH 64
#define NMID 62
#define SCL 0.125f
#define NEGV (-1000000000.0f)

// ------------------- device scratch (.bss, no allocation) -------------------
__device__ float g_h[SQ * DM];
__device__ float g_q[SQ * DM];
__device__ float g_k[SQ * DM];
__device__ float g_v[SQ * DM];
__device__ float g_attn[SQ * DM];
__device__ float g_proj[SQ * DM];
__device__ float g_ffn[SQ * FFD];
__device__ float g_gsc[NH * 2 * 64 * SQ];
__device__ float g_h1[512];

struct PlanParam { unsigned char rnd[NH][NMID][3]; };

// ------------------- host-side numpy MT19937 replication --------------------
namespace {
struct MT {
    uint32_t mt[624]; int mti;
    void seed(uint32_t s) {
        mt[0] = s;
        for (int i = 1; i < 624; i++)
            mt[i] = 1812433253u * (mt[i-1] ^ (mt[i-1] >> 30)) + (uint32_t)i;
        mti = 624;
    }
    uint32_t next() {
        if (mti >= 624) {
            for (int i = 0; i < 624; i++) {
                uint32_t y = (mt[i] & 0x80000000u) | (mt[(i+1)%624] & 0x7fffffffu);
                mt[i] = mt[(i+397)%624] ^ (y >> 1) ^ ((y & 1u) ? 0x9908b0dfu : 0u);
            }
            mti = 0;
        }
        uint32_t y = mt[mti++];
        y ^= y >> 11; y ^= (y << 7) & 0x9d2c5680u;
        y ^= (y << 15) & 0xefc60000u; y ^= y >> 18;
        return y;
    }
    uint32_t interval(uint32_t mx) {
        if (!mx) return 0;
        uint32_t m = mx;
        m |= m>>1; m |= m>>2; m |= m>>4; m |= m>>8; m |= m>>16;
        uint32_t v;
        while ((v = (next() & m)) > mx) {}
        return v;
    }
};
PlanParam build_plan() {
    PlanParam P; MT r; r.seed(0u);
    for (int h = 0; h < NH; h++)
        for (int i = 1; i <= NMID; i++) {
            bool inb[64] = {};
            inb[0] = inb[i-1] = inb[i] = inb[i+1] = inb[63] = true;
            int cand[64], nc = 0;
            for (int j = 1; j < 63; j++) if (!inb[j]) cand[nc++] = j;
            int perm[64];
            for (int t = 0; t < nc; t++) perm[t] = t;
            for (int t = nc - 1; t > 0; t--) {
                int j2 = (int)r.interval((uint32_t)t);
                int tmp = perm[t]; perm[t] = perm[j2]; perm[j2] = tmp;
            }
            for (int q = 0; q < 3; q++)
                P.rnd[h][i-1][q] = (unsigned char)cand[perm[q]];
        }
    return P;
}
PlanParam g_plan = build_plan();
} // namespace

// ------------------------------ device helpers ------------------------------
__device__ __forceinline__ float gelu_t(float x) {
    float x3 = x * x * x;
    return 0.5f * x * (1.0f + tanhf(0.7978845608028654f * (x + 0.044715f * x3)));
}
// load 64x64 f32 tile into smem pitch 65; needs 256 threads
__device__ __forceinline__ void ldtile(float* dst, const float* src, int stride) {
    int t = threadIdx.x, r = t >> 2, c0 = (t & 3) * 16;
    const float* s = src + (size_t)r * stride + c0;
    float* d = dst + r * 65 + c0;
#pragma unroll
    for (int u = 0; u < 4; u++) {
        float4 v = *(const float4*)(s + u * 4);
        d[u*4+0] = v.x; d[u*4+1] = v.y; d[u*4+2] = v.z; d[u*4+3] = v.w;
    }
}

// --------------------------------- SGEMM ------------------------------------
// C[M,N] = act(A[M,K] @ B[K,N] + bias). 128x64 tile, 256 thr, 8x4/thread.
__global__ __launch_bounds__(256)
void sgemm(const float* __restrict__ A, const float* __restrict__ B,
           const float* __restrict__ bias, float* __restrict__ C,
           int M, int N, int K, int act) {
    __shared__ float As[16][132];
    __shared__ float Bs[16][64];
    int tid = threadIdx.x, tx = tid & 15, ty = tid >> 4;
    int rb = blockIdx.y * 128, cb = blockIdx.x * 64;
    int lr = tid >> 2, lc = (tid & 3) * 4;
    int bkr = tid >> 4, bkc = (tid & 15) * 4;
    const float* Ap0 = A + (size_t)(rb + lr) * K + lc;
    const float* Ap1 = A + (size_t)(rb + lr + 64) * K + lc;
    const float* Bp = B + (size_t)bkr * N + cb + bkc;
    float acc[8][4];
#pragma unroll
    for (int i = 0; i < 8; i++)
#pragma unroll
        for (int j = 0; j < 4; j++) acc[i][j] = 0.f;
    for (int k0 = 0; k0 < K; k0 += 16) {
        float4 a0 = *(const float4*)(Ap0 + k0);
        float4 a1 = *(const float4*)(Ap1 + k0);
        float4 b0 = *(const float4*)(Bp + (size_t)k0 * N);
        As[lc+0][lr] = a0.x; As[lc+1][lr] = a0.y; As[lc+2][lr] = a0.z; As[lc+3][lr] = a0.w;
        As[lc+0][lr+64] = a1.x; As[lc+1][lr+64] = a1.y; As[lc+2][lr+64] = a1.z; As[lc+3][lr+64] = a1.w;
        *(float4*)&Bs[bkr][bkc] = b0;
        __syncthreads();
#pragma unroll
        for (int kk = 0; kk < 16; kk++) {
            float4 av0 = *(const float4*)&As[kk][ty*8];
            float4 av1 = *(const float4*)&As[kk][ty*8+4];
            float4 bv = *(const float4*)&Bs[kk][tx*4];
            float a[8] = {av0.x,av0.y,av0.z,av0.w,av1.x,av1.y,av1.z,av1.w};
            float b[4] = {bv.x,bv.y,bv.z,bv.w};
#pragma unroll
            for (int i = 0; i < 8; i++)
#pragma unroll
                for (int j = 0; j < 4; j++) acc[i][j] += a[i] * b[j];
        }
        __syncthreads();
    }
#pragma unroll
    for (int i = 0; i < 8; i++) {
        int row = rb + ty * 8 + i;
#pragma unroll
        for (int j = 0; j < 4; j++) {
            int col = cb + tx * 4 + j;
            float v = acc[i][j] + bias[col];
            if (act) v = gelu_t(v);
            C[(size_t)row * N + col] = v;
        }
    }
}

// ----------------------- residual add + LayerNorm ---------------------------
__global__ __launch_bounds__(256)
void add_ln(float* __restrict__ out, const float* __restrict__ a,
            const float* __restrict__ b, const float* __restrict__ pos,
            const float* __restrict__ tok, const float* __restrict__ g,
            const float* __restrict__ be) {
    int row = blockIdx.x, tid = threadIdx.x;
    __shared__ float sw[8];
    __shared__ float sb;
    float v[3], s = 0.f;
#pragma unroll
    for (int u = 0; u < 3; u++) {
        int c = tid + u * 256;
        float t = a[(size_t)row * DM + c];
        if (b) t += b[(size_t)row * DM + c];
        if (pos) t += pos[(size_t)row * DM + c];
        if (tok) t += tok[c];
        v[u] = t; s += t;
    }
#pragma unroll
    for (int o = 16; o; o >>= 1) s += __shfl_xor_sync(~0u, s, o);
    if (!(tid & 31)) sw[tid >> 5] = s;
    __syncthreads();
    if (!tid) { float t = 0; for (int w = 0; w < 8; w++) t += sw[w]; sb = t / 768.f; }
    __syncthreads();
    float mean = sb, q = 0.f;
#pragma unroll
    for (int u = 0; u < 3; u++) { float d = v[u] - mean; q += d * d; }
#pragma unroll
    for (int o = 16; o; o >>= 1) q += __shfl_xor_sync(~0u, q, o);
    __syncthreads();
    if (!(tid & 31)) sw[tid >> 5] = q;
    __syncthreads();
    if (!tid) { float t = 0; for (int w = 0; w < 8; w++) t += sw[w]; sb = t / 768.f; }
    __syncthreads();
    float inv = rsqrtf(sb + 1e-12f);
#pragma unroll
    for (int u = 0; u < 3; u++) {
        int c = tid + u * 256;
        out[(size_t)row * DM + c] = (v[u] - mean) * inv * g[c] + be[c];
    }
}

// ----------------------- global attention (blocks 0, 63) --------------------
__global__ __launch_bounds__(256)
void gscore(const float* __restrict__ Q, const float* __restrict__ K,
            const int* __restrict__ am, float* __restrict__ gsc) {
    int kb = blockIdx.x, hg = blockIdx.y, h = hg >> 1;
    int qb = (hg & 1) ? (SQ - 64) : 0;
    __shared__ float Qs[64 * 65];
    __shared__ float Ks[64 * 65];
    ldtile(Qs, Q + (size_t)qb * DM + h * DH, DM);
    ldtile(Ks, K + (size_t)(kb * 64) * DM + h * DH, DM);
    __syncthreads();
    int tid = threadIdx.x, tx = tid & 15, ty = tid >> 4;
    float acc[4][4];
#pragma unroll
    for (int i = 0; i < 4; i++)
#pragma unroll
        for (int j = 0; j < 4; j++) acc[i][j] = 0.f;
#pragma unroll 4
    for (int d = 0; d < 64; d++) {
        float qv[4], kv[4];
#pragma unroll
        for (int i = 0; i < 4; i++) qv[i] = Qs[(ty*4+i)*65 + d];
#pragma unroll
        for (int j = 0; j < 4; j++) kv[j] = Ks[(tx*4+j)*65 + d];
#pragma unroll
        for (int i = 0; i < 4; i++)
#pragma unroll
            for (int j = 0; j < 4; j++) acc[i][j] += qv[i] * kv[j];
    }
#pragma unroll
    for (int j = 0; j < 4; j++) {
        int kc = kb * 64 + tx * 4 + j;
        bool ok = am[kc] > 0;
#pragma unroll
        for (int i = 0; i < 4; i++)
            gsc[(size_t)(hg * 64 + ty * 4 + i) * SQ + kc] = ok ? acc[i][j] * SCL : NEGV;
    }
}

__global__ __launch_bounds__(256)
void gsoftmax(float* __restrict__ gsc) {
    int row = blockIdx.x, tid = threadIdx.x;
    float* p = gsc + (size_t)row * SQ;
    __shared__ float sw[8];
    __shared__ float sb;
    float mx = -3.4e38f;
    for (int c = tid; c < SQ; c += 256) mx = fmaxf(mx, p[c]);
#pragma unroll
    for (int o = 16; o; o >>= 1) mx = fmaxf(mx, __shfl_xor_sync(~0u, mx, o));
    if (!(tid & 31)) sw[tid >> 5] = mx;
    __syncthreads();
    if (!tid) { float t = sw[0]; for (int w = 1; w < 8; w++) t = fmaxf(t, sw[w]); sb = t; }
    __syncthreads();
    mx = sb;
    float s = 0.f;
    for (int c = tid; c < SQ; c += 256) { float e = expf(p[c] - mx); p[c] = e; s += e; }
#pragma unroll
    for (int o = 16; o; o >>= 1) s += __shfl_xor_sync(~0u, s, o);
    __syncthreads();
    if (!(tid & 31)) sw[tid >> 5] = s;
    __syncthreads();
    if (!tid) { float t = 0; for (int w = 0; w < 8; w++) t += sw[w]; sb = t; }
    __syncthreads();
    float inv = 1.f / sb;
    for (int c = tid; c < SQ; c += 256) p[c] *= inv;
}

__global__ __launch_bounds__(256)
void gpv(const float* __restrict__ gsc, const float* __restrict__ V,
         float* __restrict__ O) {
    int hg = blockIdx.x, h = hg >> 1;
    int qb = (hg & 1) ? (SQ - 64) : 0;
    __shared__ float Ps[64 * 65];
    __shared__ float Vs[64 * 65];
    int tid = threadIdx.x, tx = tid & 15, ty = tid >> 4;
    float acc[4][4];
#pragma unroll
    for (int i = 0; i < 4; i++)
#pragma unroll
        for (int j = 0; j < 4; j++) acc[i][j] = 0.f;
    for (int kb = 0; kb < 64; kb++) {
        ldtile(Ps, gsc + (size_t)(hg * 64) * SQ + kb * 64, SQ);
        ldtile(Vs, V + (size_t)(kb * 64) * DM + h * DH, DM);
        __syncthreads();
#pragma unroll 4
        for (int kk = 0; kk < 64; kk++) {
            float pv[4], vv[4];
#pragma unroll
            for (int i = 0; i < 4; i++) pv[i] = Ps[(ty*4+i)*65 + kk];
#pragma unroll
            for (int j = 0; j < 4; j++) vv[j] = Vs[kk*65 + tx*4 + j];
#pragma unroll
            for (int i = 0; i < 4; i++)
#pragma unroll
                for (int j = 0; j < 4; j++) acc[i][j] += pv[i] * vv[j];
        }
        __syncthreads();
    }
#pragma unroll
    for (int i = 0; i < 4; i++)
#pragma unroll
        for (int j = 0; j < 4; j++)
            O[(size_t)(qb + ty*4 + i) * DM + h * DH + tx*4 + j] = acc[i][j];
}

// ----------------------- middle (sparse) attention --------------------------
// one CTA per (mid-block, head); smem: q(64*65) + scores(64*520) + kv(64*65)
__global__ __launch_bounds__(256)
void midattn(const float* __restrict__ Q, const float* __restrict__ K,
             const float* __restrict__ V, const int* __restrict__ am,
             float* __restrict__ O, PlanParam plan) {
    int im = blockIdx.x, h = blockIdx.y;
    int i = im + 1;
    extern __shared__ float sm[];
    float* qs = sm;              // 64*65
    float* sc = sm + 64*65;      // 64*520
    float* kv = sc + 64*520;     // 64*65
    int tid = threadIdx.x, tx = tid & 15, ty = tid >> 4;
    int blk[8];
    blk[0] = 0; blk[1] = i - 1; blk[2] = i; blk[3] = i + 1; blk[4] = 63;
    blk[5] = plan.rnd[h][im][0]; blk[6] = plan.rnd[h][im][1]; blk[7] = plan.rnd[h][im][2];
    bool vld[8] = {true, i != 1, true, true, i != 62, true, true, true};

    ldtile(qs, Q + (size_t)(i * 64) * DM + h * DH, DM);
    for (int c = 0; c < 8; c++) {
        __syncthreads();
        ldtile(kv, K + (size_t)(blk[c] * 64) * DM + h * DH, DM);
        __syncthreads();
        float acc[4][4];
#pragma unroll
        for (int a = 0; a < 4; a++)
#pragma unroll
            for (int b = 0; b < 4; b++) acc[a][b] = 0.f;
#pragma unroll 4
        for (int d = 0; d < 64; d++) {
            float qv[4], kk[4];
#pragma unroll
            for (int a = 0; a < 4; a++) qv[a] = qs[(ty*4+a)*65 + d];
#pragma unroll
            for (int b = 0; b < 4; b++) kk[b] = kv[(tx*4+b)*65 + d];
#pragma unroll
            for (int a = 0; a < 4; a++)
#pragma unroll
                for (int b = 0; b < 4; b++) acc[a][b] += qv[a] * kk[b];
        }
#pragma unroll
        for (int b = 0; b < 4; b++) {
            bool ok = vld[c] && (am[blk[c] * 64 + tx*4 + b] > 0);
#pragma unroll
            for (int a = 0; a < 4; a++)
                sc[(ty*4+a)*520 + c*64 + tx*4 + b] = ok ? acc[a][b] * SCL : NEGV;
        }
    }
    __syncthreads();
    // softmax: 4 threads per row
    {
        int row = tid >> 2, sub = tid & 3;
        float* sr = sc + row * 520;
        float mx = -3.4e38f;
        for (int c = sub; c < 512; c += 4) mx = fmaxf(mx, sr[c]);
        mx = fmaxf(mx, __shfl_xor_sync(~0u, mx, 1));
        mx = fmaxf(mx, __shfl_xor_sync(~0u, mx, 2));
        float s = 0.f;
        for (int c = sub; c < 512; c += 4) { float e = expf(sr[c] - mx); sr[c] = e; s += e; }
        s += __shfl_xor_sync(~0u, s, 1);
        s += __shfl_xor_sync(~0u, s, 2);
        float inv = 1.f / s;
        for (int c = sub; c < 512; c += 4) sr[c] *= inv;
    }
    // PV
    float oac[4][4];
#pragma unroll
    for (int a = 0; a < 4; a++)
#pragma unroll
        for (int b = 0; b < 4; b++) oac[a][b] = 0.f;
    for (int c = 0; c < 8; c++) {
        __syncthreads();
        ldtile(kv, V + (size_t)(blk[c] * 64) * DM + h * DH, DM);
        __syncthreads();
#pragma unroll 4
        for (int kk = 0; kk < 64; kk++) {
            float pv[4], vv[4];
#pragma unroll
            for (int a = 0; a < 4; a++) pv[a] = sc[(ty*4+a)*520 + c*64 + kk];
#pragma unroll
            for (int b = 0; b < 4; b++) vv[b] = kv[kk*65 + tx*4 + b];
#pragma unroll
            for (int a = 0; a < 4; a++)
#pragma unroll
                for (int b = 0; b < 4; b++) oac[a][b] += pv[a] * vv[b];
        }
    }
#pragma unroll
    for (int a = 0; a < 4; a++)
#pragma unroll
        for (int b = 0; b < 4; b++)
            O[(size_t)(i*64 + ty*4 + a) * DM + h * DH + tx*4 + b] = oac[a][b];
}

// ------------------------------ classifier ----------------------------------
__global__ __launch_bounds__(512)
void cls_fc1(const float* __restrict__ h, const float* __restrict__ W,
             const float* __restrict__ b, float* __restrict__ o) {
    int n = threadIdx.x;
    float s = b[n];
    for (int k = 0; k < DM; k++) s += h[k] * W[(size_t)k * 512 + n];
    o[n] = fmaxf(s, 0.f);
}
__global__ __launch_bounds__(256)
void cls_fc2(const float* __restrict__ h1, const float* __restrict__ W,
             const float* __restrict__ b, float* __restrict__ o) {
    int n = blockIdx.x * 256 + threadIdx.x;
    if (n >= 2000) return;
    float s = b[n];
    for (int k = 0; k < 512; k++) s += h1[k] * W[(size_t)k * 2000 + n];
    o[n] = s;
}

// ------------------------------ launch --------------------------------------
extern "C" void kernel_launch(void* const* d_in, const int* in_sizes, int n_in,
                              void* d_out, int out_size) {
    const float* x    = (const float*)d_in[0];
    const int*   am   = (const int*)d_in[1];
    const float* Wp   = (const float*)d_in[2];
    const float* bp   = (const float*)d_in[3];
    const float* pos  = (const float*)d_in[4];
    const float* tok  = (const float*)d_in[5];
    const float* lng  = (const float*)d_in[6];
    const float* lnb  = (const float*)d_in[7];
    const float* Wq   = (const float*)d_in[8];
    const float* bq   = (const float*)d_in[9];
    const float* Wk   = (const float*)d_in[10];
    const float* bk   = (const float*)d_in[11];
    const float* Wv   = (const float*)d_in[12];
    const float* bv   = (const float*)d_in[13];
    const float* Wo   = (const float*)d_in[14];
    const float* bo   = (const float*)d_in[15];
    const float* l1g  = (const float*)d_in[16];
    const float* l1b  = (const float*)d_in[17];
    const float* W1   = (const float*)d_in[18];
    const float* b1f  = (const float*)d_in[19];
    const float* W2   = (const float*)d_in[20];
    const float* b2f  = (const float*)d_in[21];
    const float* l2g  = (const float*)d_in[22];
    const float* l2b  = (const float*)d_in[23];
    const float* Wc1  = (const float*)d_in[24];
    const float* bc1  = (const float*)d_in[25];
    const float* Wc2  = (const float*)d_in[26];
    const float* bc2  = (const float*)d_in[27];

    float *h, *q, *k, *v, *attn, *proj, *ffn, *gsc, *h1;
    cudaGetSymbolAddress((void**)&h, g_h);
    cudaGetSymbolAddress((void**)&q, g_q);
    cudaGetSymbolAddress((void**)&k, g_k);
    cudaGetSymbolAddress((void**)&v, g_v);
    cudaGetSymbolAddress((void**)&attn, g_attn);
    cudaGetSymbolAddress((void**)&proj, g_proj);
    cudaGetSymbolAddress((void**)&ffn, g_ffn);
    cudaGetSymbolAddress((void**)&gsc, g_gsc);
    cudaGetSymbolAddress((void**)&h1, g_h1);

    int smmid = (64*65 + 64*520 + 64*65) * 4;
    cudaFuncSetAttribute(midattn, cudaFuncAttributeMaxDynamicSharedMemorySize, smmid);

    dim3 gP(DM/64, SQ/128);   // N=768
    dim3 gF(FFD/64, SQ/128);  // N=3072

    // embedding projection + LN
    sgemm<<<gP, 256>>>(x, Wp, bp, proj, SQ, DM, 1280, 0);
    add_ln<<<SQ, 256>>>(h, proj, nullptr, pos, tok, lng, lnb);

    for (int l = 0; l < 12; l++) {
        const float* wq = Wq + (size_t)l*DM*DM; const float* bql = bq + (size_t)l*DM;
        const float* wk = Wk + (size_t)l*DM*DM; const float* bkl = bk + (size_t)l*DM;
        const float* wv = Wv + (size_t)l*DM*DM; const float* bvl = bv + (size_t)l*DM;
        const float* wo = Wo + (size_t)l*DM*DM; const float* bol = bo + (size_t)l*DM;
        const float* w1 = W1 + (size_t)l*DM*FFD; const float* b1l = b1f + (size_t)l*FFD;
        const float* w2 = W2 + (size_t)l*FFD*DM; const float* b2l = b2f + (size_t)l*DM;

        sgemm<<<gP, 256>>>(h, wq, bql, q, SQ, DM, DM, 0);
        sgemm<<<gP, 256>>>(h, wk, bkl, k, SQ, DM, DM, 0);
        sgemm<<<gP, 256>>>(h, wv, bvl, v, SQ, DM, DM, 0);

        gscore<<<dim3(64, 24), 256>>>(q, k, am, gsc);
        gsoftmax<<<24 * 64, 256>>>(gsc);
        gpv<<<24, 256>>>(gsc, v, attn);
        midattn<<<dim3(62, 12), 256, smmid>>>(q, k, v, am, attn, g_plan);

        sgemm<<<gP, 256>>>(attn, wo, bol, proj, SQ, DM, DM, 0);
        add_ln<<<SQ, 256>>>(h, h, proj, nullptr, nullptr, l1g + (size_t)l*DM, l1b + (size_t)l*DM);
        sgemm<<<gF, 256>>>(h, w1, b1l, ffn, SQ, FFD, DM, 1);
        sgemm<<<gP, 256>>>(ffn, w2, b2l, proj, SQ, DM, FFD, 0);
        add_ln<<<SQ, 256>>>(h, h, proj, nullptr, nullptr, l2g + (size_t)l*DM, l2b + (size_t)l*DM);
    }

    cls_fc1<<<1, 512>>>(h, Wc1, bc1, h1);
    cls_fc2<<<8, 256>>>(h1, Wc2, bc2, (float*)d_out);
}